// round 12
// baseline (speedup 1.0000x reference)
#include <cuda_runtime.h>
#include <cuda_bf16.h>
#include <math.h>
#include <stdint.h>

#define Bb 2
#define SS 2048
#define DD 2048
#define HH 16
#define HDm 128
#define MM (Bb*SS)   // 4096

// ---------------------------------------------------------------------------
// Device-global scratch (no allocations allowed)
// ---------------------------------------------------------------------------
__device__ __align__(16) __nv_bfloat16 g_Xh[(size_t)MM*DD],  g_Xl[(size_t)MM*DD];
__device__ __align__(16) __nv_bfloat16 g_Wqh[(size_t)DD*DD], g_Wql[(size_t)DD*DD];
__device__ __align__(16) __nv_bfloat16 g_Wkh[(size_t)DD*DD], g_Wkl[(size_t)DD*DD];
__device__ __align__(16) __nv_bfloat16 g_Wvh[(size_t)DD*DD], g_Wvl[(size_t)DD*DD];
__device__ __align__(16) __nv_bfloat16 g_Woh[(size_t)DD*DD], g_Wol[(size_t)DD*DD];
__device__ __align__(16) __nv_bfloat16 g_Ch[(size_t)MM*DD],  g_Cl[(size_t)MM*DD];

// post-RoPE Q/K in bf16 hi/lo, [b,h,s,d]
__device__ __align__(16) __nv_bfloat16 g_Qh[(size_t)MM*DD], g_Ql[(size_t)MM*DD];
__device__ __align__(16) __nv_bfloat16 g_Kh[(size_t)MM*DD], g_Kl[(size_t)MM*DD];
// V transposed, [b,h,d,s], bf16 hi/lo
__device__ __align__(16) __nv_bfloat16 g_VhT[(size_t)MM*DD], g_VlT[(size_t)MM*DD];

// ---------------------------------------------------------------------------
// helpers (arch-portable PTX only)
// ---------------------------------------------------------------------------
__device__ __forceinline__ uint32_t smem_u32(const void* p) {
    uint32_t a;
    asm("{ .reg .u64 t; cvta.to.shared.u64 t, %1; cvt.u32.u64 %0, t; }"
        : "=r"(a) : "l"(p));
    return a;
}

__device__ __forceinline__ void mma16816(float* c, const uint32_t* a, const uint32_t* b) {
    asm volatile(
        "mma.sync.aligned.m16n8k16.row.col.f32.bf16.bf16.f32 "
        "{%0,%1,%2,%3}, {%4,%5,%6,%7}, {%8,%9}, {%0,%1,%2,%3};"
        : "+f"(c[0]), "+f"(c[1]), "+f"(c[2]), "+f"(c[3])
        : "r"(a[0]), "r"(a[1]), "r"(a[2]), "r"(a[3]), "r"(b[0]), "r"(b[1]));
}

__device__ __forceinline__ void ldsm4(uint32_t* r, uint32_t addr) {
    asm volatile("ldmatrix.sync.aligned.m8n8.x4.shared.b16 {%0,%1,%2,%3}, [%4];"
        : "=r"(r[0]), "=r"(r[1]), "=r"(r[2]), "=r"(r[3]) : "r"(addr));
}

__device__ __forceinline__ void cpasync16(uint32_t dst, const void* src) {
    asm volatile("cp.async.cg.shared.global [%0], [%1], 16;\n" :: "r"(dst), "l"(src) : "memory");
}

__device__ __forceinline__ uint32_t pack_bf2(float a, float b) {
    __nv_bfloat162 t;
    t.x = __float2bfloat16(a);
    t.y = __float2bfloat16(b);
    return *(uint32_t*)&t;
}

// ---------------------------------------------------------------------------
// fp32 -> bf16 hi/lo splitter
// ---------------------------------------------------------------------------
template<int SEL>
__global__ __launch_bounds__(256) void split_kernel(const float* __restrict__ src, int n4)
{
    const int i = blockIdx.x * 256 + threadIdx.x;
    if (i >= n4) return;
    __nv_bfloat16* hi = (SEL==0) ? g_Xh : (SEL==1) ? g_Wqh : (SEL==2) ? g_Wkh
                      : (SEL==3) ? g_Wvh : g_Woh;
    __nv_bfloat16* lo = (SEL==0) ? g_Xl : (SEL==1) ? g_Wql : (SEL==2) ? g_Wkl
                      : (SEL==3) ? g_Wvl : g_Wol;
    const float4 v = ((const float4*)src)[i];
    __nv_bfloat162 h0, h1, l0, l1;
    h0.x = __float2bfloat16(v.x); h0.y = __float2bfloat16(v.y);
    h1.x = __float2bfloat16(v.z); h1.y = __float2bfloat16(v.w);
    l0.x = __float2bfloat16(v.x - __bfloat162float(h0.x));
    l0.y = __float2bfloat16(v.y - __bfloat162float(h0.y));
    l1.x = __float2bfloat16(v.z - __bfloat162float(h1.x));
    l1.y = __float2bfloat16(v.w - __bfloat162float(h1.y));
    ((__nv_bfloat162*)hi)[i*2]   = h0;
    ((__nv_bfloat162*)hi)[i*2+1] = h1;
    ((__nv_bfloat162*)lo)[i*2]   = l0;
    ((__nv_bfloat162*)lo)[i*2+1] = l1;
}

// ---------------------------------------------------------------------------
// HMMA GEMM mainloop. 128x128 tile, BK=32, 128 threads (4 warps, warp tile
// 64x64), 2-stage cp.async, ONE barrier per chunk. ldmatrix fragments,
// hi/lo loaded once per k-step, reused across the 3 split passes.
// ---------------------------------------------------------------------------
#define TILE_B 10240
#define STAGE_BYTES (4*TILE_B)
#define GSMEM_TOTAL (2*STAGE_BYTES)

__device__ __forceinline__ void stage_load(char* smc, int stage,
    const __nv_bfloat16* Ah, const __nv_bfloat16* Al,
    const __nv_bfloat16* Bh, const __nv_bfloat16* Bl,
    size_t arow, size_t brow, int k0, int tid)
{
    const __nv_bfloat16* srcs[4] = {Ah, Al, Bh, Bl};
#pragma unroll
    for (int t = 0; t < 4; t++) {
        const size_t rb = (t < 2) ? arow : brow;
        const __nv_bfloat16* s = srcs[t];
        char* base = smc + stage*STAGE_BYTES + t*TILE_B;
#pragma unroll
        for (int h = 0; h < 4; h++) {
            const int c = tid + h*128;          // 0..511
            const int row = c >> 2, col = c & 3;
            cpasync16(smem_u32(base + row*80 + col*16), s + (rb + row)*(size_t)DD + k0 + col*8);
        }
    }
}

__device__ __forceinline__ void gemm_mainloop(char* smc,
    const __nv_bfloat16* Ah, const __nv_bfloat16* Al,
    const __nv_bfloat16* Bh, const __nv_bfloat16* Bl,
    size_t arow, size_t brow, int tid, float cacc[4][8][4])
{
    const int wid = tid >> 5, lane = tid & 31;
    const int wm = wid >> 1, wn = wid & 1;     // 2x2 warp grid, 64x64 tiles
    const int g = lane >> 2, tg = lane & 3;

    // ldmatrix lane addressing
    const int rowA = (lane & 7) + ((lane >> 3) & 1) * 8;
    const int khA  = lane >> 4;
    const int rowB = ((lane >> 4) & 1) * 8 + (lane & 7);
    const int khB  = (lane >> 3) & 1;

    const uint32_t sb = smem_u32(smc);
    const uint32_t aoff = (uint32_t)((wm*64 + rowA)*80 + khA*16);
    const uint32_t boff = (uint32_t)((wn*64 + rowB)*80 + khB*16);

    stage_load(smc, 0, Ah, Al, Bh, Bl, arow, brow, 0, tid);
    asm volatile("cp.async.commit_group;\n" ::: "memory");

    for (int ch = 0; ch < 64; ch++) {
        asm volatile("cp.async.wait_group 0;\n" ::: "memory");
        __syncthreads();   // data of stage ch&1 visible; all warps done with stage (ch+1)&1
        if (ch + 1 < 64) {
            stage_load(smc, (ch+1) & 1, Ah, Al, Bh, Bl, arow, brow, (ch+1)*32, tid);
            asm volatile("cp.async.commit_group;\n" ::: "memory");
        }

        const uint32_t st = sb + (ch & 1)*STAGE_BYTES;
#pragma unroll
        for (int kk2 = 0; kk2 < 2; kk2++) {
            const uint32_t kb = kk2*32;
            uint32_t ah[4][4], al[4][4];
#pragma unroll
            for (int mt = 0; mt < 4; mt++) {
                ldsm4(ah[mt], st + aoff + mt*(16*80) + kb);
                ldsm4(al[mt], st + TILE_B + aoff + mt*(16*80) + kb);
            }
#pragma unroll
            for (int p = 0; p < 4; p++) {
                uint32_t bhf[4], blf[4];
                ldsm4(bhf, st + 2*TILE_B + boff + p*(16*80) + kb);
                ldsm4(blf, st + 3*TILE_B + boff + p*(16*80) + kb);
#pragma unroll
                for (int mt = 0; mt < 4; mt++) {
                    mma16816(cacc[mt][2*p],   ah[mt], bhf);
                    mma16816(cacc[mt][2*p+1], ah[mt], bhf+2);
                    mma16816(cacc[mt][2*p],   ah[mt], blf);
                    mma16816(cacc[mt][2*p+1], ah[mt], blf+2);
                    mma16816(cacc[mt][2*p],   al[mt], bhf);
                    mma16816(cacc[mt][2*p+1], al[mt], bhf+2);
                }
            }
        }
    }

    // accumulators -> smem epi buffer [128][132]
    __syncthreads();
    float* epi = (float*)smc;
#pragma unroll
    for (int mt = 0; mt < 4; mt++)
#pragma unroll
        for (int nt = 0; nt < 8; nt++) {
            const int r0 = wm*64 + mt*16 + g;
            const int c0 = wn*64 + nt*8 + 2*tg;
            *(float2*)&epi[r0*132 + c0]     = make_float2(cacc[mt][nt][0], cacc[mt][nt][1]);
            *(float2*)&epi[(r0+8)*132 + c0] = make_float2(cacc[mt][nt][2], cacc[mt][nt][3]);
        }
    __syncthreads();
}

// Merged Q/K/V projection GEMM: blockIdx.z selects weight + epilogue.
__global__ __launch_bounds__(128, 2) void gemm_qkv(const float* __restrict__ cosT,
                                                   const float* __restrict__ sinT)
{
    extern __shared__ char smc[];
    const int tid = threadIdx.x;
    const int bn = blockIdx.x, bm = blockIdx.y, sel = blockIdx.z;

    const __nv_bfloat16* Bh = (sel == 0) ? g_Wqh : (sel == 1) ? g_Wkh : g_Wvh;
    const __nv_bfloat16* Bl = (sel == 0) ? g_Wql : (sel == 1) ? g_Wkl : g_Wvl;

    float cacc[4][8][4];
#pragma unroll
    for (int mt = 0; mt < 4; mt++)
#pragma unroll
        for (int nt = 0; nt < 8; nt++)
#pragma unroll
            for (int q = 0; q < 4; q++) cacc[mt][nt][q] = 0.f;

    gemm_mainloop(smc, g_Xh, g_Xl, Bh, Bl, (size_t)bm*128, (size_t)bn*128, tid, cacc);

    float* epi = (float*)smc;
    if (sel <= 1) {
        __nv_bfloat16* Oh = (sel == 0) ? g_Qh : g_Kh;
        __nv_bfloat16* Ol = (sel == 0) ? g_Ql : g_Kl;
        for (int i = tid; i < 128*128; i += 128) {
            const int r = i >> 7, c = i & 127;
            const float v = epi[r*132 + c];
            const int m = bm*128 + r;
            const int b = m >> 11, s = m & 2047;
            const float cs = cosT[s*HDm + c];
            const float sn = sinT[s*HDm + c];
            const float o  = epi[r*132 + (c ^ 64)];
            const float res = (c < 64) ? (v*cs - o*sn) : (v*cs + o*sn);
            const size_t idx = ((size_t)(b*HH + bn)*SS + s)*HDm + c;
            const __nv_bfloat16 hh = __float2bfloat16(res);
            Oh[idx] = hh;
            Ol[idx] = __float2bfloat16(res - __bfloat162float(hh));
        }
    } else {
        const int b = (bm*128) >> 11;
        const int s0 = (bm*128) & 2047;
        for (int i = tid; i < 128*16; i += 128) {
            const int c  = i & 127;
            const int r0 = (i >> 7)*8;
            __nv_bfloat16 hbuf[8], lbuf[8];
#pragma unroll
            for (int j = 0; j < 8; j++) {
                const float v = epi[(r0+j)*132 + c];
                hbuf[j] = __float2bfloat16(v);
                lbuf[j] = __float2bfloat16(v - __bfloat162float(hbuf[j]));
            }
            const size_t dst = ((size_t)(b*HH + bn)*HDm + c)*SS + s0 + r0;
            *(uint4*)&g_VhT[dst] = *(uint4*)hbuf;
            *(uint4*)&g_VlT[dst] = *(uint4*)lbuf;
        }
    }
}

// Output GEMM: ctx @ Wo^T -> fp32 out
__global__ __launch_bounds__(128, 2) void gemm_out(float* __restrict__ outp)
{
    extern __shared__ char smc[];
    const int tid = threadIdx.x;
    const int bn = blockIdx.x, bm = blockIdx.y;

    float cacc[4][8][4];
#pragma unroll
    for (int mt = 0; mt < 4; mt++)
#pragma unroll
        for (int nt = 0; nt < 8; nt++)
#pragma unroll
            for (int q = 0; q < 4; q++) cacc[mt][nt][q] = 0.f;

    gemm_mainloop(smc, g_Ch, g_Cl, g_Woh, g_Wol, (size_t)bm*128, (size_t)bn*128, tid, cacc);

    float* epi = (float*)smc;
    for (int i = tid; i < 128*128; i += 128) {
        const int r = i >> 7, c = i & 127;
        outp[(size_t)(bm*128 + r)*DD + bn*128 + c] = epi[r*132 + c];
    }
}

// ---------------------------------------------------------------------------
// Flash attention, mma.sync bf16 3x-split, ldmatrix fragments.
// 256 threads (8 warps), 128 q rows/CTA, 64-row K/V tiles double-buffered,
// ONE barrier per tile.
// ---------------------------------------------------------------------------
#define QROWB 272
#define VROWB 144
#define OFF_QH 0
#define OFF_QL (128*QROWB)                 // 34816
#define STG0   (2*128*QROWB)               // 69632
#define SOFF_KH 0
#define SOFF_KL (64*QROWB)                 // 17408
#define SOFF_VH (2*64*QROWB)               // 34816
#define SOFF_VL (2*64*QROWB + 128*VROWB)   // 53248
#define STG_SZ  (2*64*QROWB + 2*128*VROWB) // 71680
#define FSMEM   (STG0 + 2*STG_SZ)          // 212992

__device__ __forceinline__ void load_kv(uint32_t sb, int stage,
                                        size_t qkb, size_t vb, int j0, int tid)
{
    const uint32_t base = sb + STG0 + stage*STG_SZ;
#pragma unroll
    for (int j = 0; j < 4; j++) {
        const int idx = j*256 + tid;
        const int row = idx >> 4, c16 = idx & 15;
        cpasync16(base + SOFF_KH + row*QROWB + c16*16, g_Kh + qkb + (size_t)(j0+row)*HDm + c16*8);
        cpasync16(base + SOFF_KL + row*QROWB + c16*16, g_Kl + qkb + (size_t)(j0+row)*HDm + c16*8);
        const int vrow = idx >> 3, c8 = idx & 7;
        cpasync16(base + SOFF_VH + vrow*VROWB + c8*16, g_VhT + vb + (size_t)vrow*SS + j0 + c8*8);
        cpasync16(base + SOFF_VL + vrow*VROWB + c8*16, g_VlT + vb + (size_t)vrow*SS + j0 + c8*8);
    }
}

__global__ __launch_bounds__(256) void flash_mma()
{
    extern __shared__ char fs[];
    const uint32_t sb = smem_u32(fs);
    const int tid = threadIdx.x, wid = tid >> 5, lane = tid & 31;
    const int gg = lane >> 2, tg = lane & 3;
    const int bh = blockIdx.y;
    const int q0 = (gridDim.x - 1 - blockIdx.x) * 128;   // heavy-first (LPT)
    const int wq = wid * 16;

    // ldmatrix lane addressing
    const int rowA = (lane & 7) + ((lane >> 3) & 1) * 8;
    const int khA  = lane >> 4;
    const int rowB = ((lane >> 4) & 1) * 8 + (lane & 7);
    const int khB  = (lane >> 3) & 1;
    const uint32_t qfoff = (uint32_t)((wq + rowA)*QROWB + khA*16);
    const uint32_t kfoff = (uint32_t)(rowB*QROWB + khB*16);
    const uint32_t vfoff = (uint32_t)(rowB*VROWB + khB*16);

    const size_t qkb = (size_t)bh * SS * HDm;   // [bh][s][d]
    const size_t vb  = (size_t)bh * HDm * SS;   // [bh][d][s]

    // load Q hi/lo (128 rows, once)
#pragma unroll
    for (int j = 0; j < 8; j++) {
        const int idx = j*256 + tid;
        const int row = idx >> 4, c16 = idx & 15;
        cpasync16(sb + OFF_QH + row*QROWB + c16*16, g_Qh + qkb + (size_t)(q0+row)*HDm + c16*8);
        cpasync16(sb + OFF_QL + row*QROWB + c16*16, g_Ql + qkb + (size_t)(q0+row)*HDm + c16*8);
    }
    asm volatile("cp.async.commit_group;\n" ::: "memory");

    const int ntiles = q0/64 + 2;
    load_kv(sb, 0, qkb, vb, 0, tid);
    asm volatile("cp.async.commit_group;\n" ::: "memory");

    float m2[2] = {-1e30f, -1e30f}, l2[2] = {0.f, 0.f};
    float oacc[16][4];
#pragma unroll
    for (int i = 0; i < 16; i++)
#pragma unroll
        for (int q = 0; q < 4; q++) oacc[i][q] = 0.f;

    const float scale = 0.08838834764831845f;

    for (int t = 0; t < ntiles; t++) {
        const int j0 = t * 64;
        asm volatile("cp.async.wait_group 0;\n" ::: "memory");
        __syncthreads();   // stage t&1 data visible; all warps done with stage (t+1)&1
        if (t + 1 < ntiles) {
            load_kv(sb, (t+1) & 1, qkb, vb, (t+1)*64, tid);
            asm volatile("cp.async.commit_group;\n" ::: "memory");
        }

        if (j0 <= q0 + wq + 15) {   // warp not fully masked
            const uint32_t stg = sb + STG0 + (t & 1)*STG_SZ;
            const uint32_t kH = stg + SOFF_KH + kfoff;
            const uint32_t kL = stg + SOFF_KL + kfoff;
            const uint32_t vH = stg + SOFF_VH + vfoff;
            const uint32_t vL = stg + SOFF_VL + vfoff;
            const uint32_t qH = sb + OFF_QH + qfoff;
            const uint32_t qL = sb + OFF_QL + qfoff;

            // ---- scores: S = Qh Kh + Qh Kl + Ql Kh ----
            float sacc[8][4];
#pragma unroll
            for (int nt = 0; nt < 8; nt++)
#pragma unroll
                for (int q = 0; q < 4; q++) sacc[nt][q] = 0.f;

#pragma unroll
            for (int kk2 = 0; kk2 < 8; kk2++) {
                const uint32_t kb = kk2*32;
                uint32_t qh[4], ql[4];
                ldsm4(qh, qH + kb);
                ldsm4(ql, qL + kb);
#pragma unroll
                for (int p = 0; p < 4; p++) {
                    uint32_t kh4[4], kl4[4];
                    ldsm4(kh4, kH + p*(16*QROWB) + kb);
                    ldsm4(kl4, kL + p*(16*QROWB) + kb);
                    mma16816(sacc[2*p],   qh, kh4);
                    mma16816(sacc[2*p+1], qh, kh4+2);
                    mma16816(sacc[2*p],   qh, kl4);
                    mma16816(sacc[2*p+1], qh, kl4+2);
                    mma16816(sacc[2*p],   ql, kh4);
                    mma16816(sacc[2*p+1], ql, kh4+2);
                }
            }

            // ---- mask + online softmax (rows gg and gg+8) ----
            float corr[2];
#pragma unroll
            for (int h2 = 0; h2 < 2; h2++) {
                const int r = q0 + wq + gg + h2*8;
                float mx = -1e30f;
#pragma unroll
                for (int nt = 0; nt < 8; nt++)
#pragma unroll
                    for (int e = 0; e < 2; e++) {
                        const int col = j0 + nt*8 + 2*tg + e;
                        float v = (col <= r) ? sacc[nt][h2*2+e]*scale : -1e30f;
                        sacc[nt][h2*2+e] = v;
                        mx = fmaxf(mx, v);
                    }
                mx = fmaxf(mx, __shfl_xor_sync(0xffffffffu, mx, 1));
                mx = fmaxf(mx, __shfl_xor_sync(0xffffffffu, mx, 2));
                const float mn = fmaxf(m2[h2], mx);
                corr[h2] = __expf(m2[h2] - mn);
                m2[h2] = mn;
                float rs = 0.f;
#pragma unroll
                for (int nt = 0; nt < 8; nt++)
#pragma unroll
                    for (int e = 0; e < 2; e++) {
                        const float p = __expf(sacc[nt][h2*2+e] - mn);
                        sacc[nt][h2*2+e] = p;
                        rs += p;
                    }
                rs += __shfl_xor_sync(0xffffffffu, rs, 1);
                rs += __shfl_xor_sync(0xffffffffu, rs, 2);
                l2[h2] = l2[h2]*corr[h2] + rs;
            }
#pragma unroll
            for (int nt2 = 0; nt2 < 16; nt2++) {
                oacc[nt2][0] *= corr[0]; oacc[nt2][1] *= corr[0];
                oacc[nt2][2] *= corr[1]; oacc[nt2][3] *= corr[1];
            }

            // ---- pack P hi/lo into A fragments (register-only) ----
            uint32_t aPh[4][4], aPl[4][4];
#pragma unroll
            for (int jp = 0; jp < 4; jp++) {
#pragma unroll
                for (int f = 0; f < 4; f++) {
                    const int nt = 2*jp + (f >> 1);
                    const int e0 = (f & 1)*2;
                    const float p0 = sacc[nt][e0], p1 = sacc[nt][e0+1];
                    const __nv_bfloat16 h0 = __float2bfloat16(p0);
                    const __nv_bfloat16 h1 = __float2bfloat16(p1);
                    __nv_bfloat162 hp; hp.x = h0; hp.y = h1;
                    aPh[jp][f] = *(uint32_t*)&hp;
                    aPl[jp][f] = pack_bf2(p0 - __bfloat162float(h0), p1 - __bfloat162float(h1));
                }
            }

            // ---- PV: oacc += Ph Vh + Ph Vl + Pl Vh ----
#pragma unroll
            for (int jp = 0; jp < 4; jp++) {
#pragma unroll
                for (int p = 0; p < 8; p++) {
                    uint32_t vh4[4], vl4[4];
                    ldsm4(vh4, vH + p*(16*VROWB) + jp*32);
                    ldsm4(vl4, vL + p*(16*VROWB) + jp*32);
                    mma16816(oacc[2*p],   aPh[jp], vh4);
                    mma16816(oacc[2*p+1], aPh[jp], vh4+2);
                    mma16816(oacc[2*p],   aPh[jp], vl4);
                    mma16816(oacc[2*p+1], aPh[jp], vl4+2);
                    mma16816(oacc[2*p],   aPl[jp], vh4);
                    mma16816(oacc[2*p+1], aPl[jp], vh4+2);
                }
            }
        }
    }

    // ---- epilogue: ctx bf16 hi/lo, [b, s, h*HD + d] ----
    const int b = bh / HH, h = bh % HH;
#pragma unroll
    for (int h2 = 0; h2 < 2; h2++) {
        const float inv = 1.f / l2[h2];
        const int r = q0 + wq + gg + h2*8;
        const size_t base = ((size_t)(b*SS + r))*DD + h*HDm;
#pragma unroll
        for (int nt2 = 0; nt2 < 16; nt2++) {
            const int d = nt2*8 + 2*tg;
            const float v0 = oacc[nt2][h2*2]   * inv;
            const float v1 = oacc[nt2][h2*2+1] * inv;
            const __nv_bfloat16 h0 = __float2bfloat16(v0);
            const __nv_bfloat16 h1 = __float2bfloat16(v1);
            __nv_bfloat162 hp; hp.x = h0; hp.y = h1;
            *(uint32_t*)&g_Ch[base + d] = *(uint32_t*)&hp;
            *(uint32_t*)&g_Cl[base + d] =
                pack_bf2(v0 - __bfloat162float(h0), v1 - __bfloat162float(h1));
        }
    }
}

// ---------------------------------------------------------------------------
extern "C" void kernel_launch(void* const* d_in, const int* in_sizes, int n_in,
                              void* d_out, int out_size)
{
    const float* x    = (const float*)d_in[0];
    const float* Wq   = (const float*)d_in[1];
    const float* Wk   = (const float*)d_in[2];
    const float* Wv   = (const float*)d_in[3];
    const float* Wo   = (const float*)d_in[4];
    const float* cosT = (const float*)d_in[5];
    const float* sinT = (const float*)d_in[6];
    float* out = (float*)d_out;

    cudaFuncSetAttribute(gemm_qkv, cudaFuncAttributeMaxDynamicSharedMemorySize, GSMEM_TOTAL);
    cudaFuncSetAttribute(gemm_out, cudaFuncAttributeMaxDynamicSharedMemorySize, GSMEM_TOTAL);
    cudaFuncSetAttribute(flash_mma, cudaFuncAttributeMaxDynamicSharedMemorySize, FSMEM);

    const int nx4 = MM * DD / 4;
    const int nw4 = DD * DD / 4;
    split_kernel<0><<<nx4 / 256, 256>>>(x,  nx4);
    split_kernel<1><<<nw4 / 256, 256>>>(Wq, nw4);
    split_kernel<2><<<nw4 / 256, 256>>>(Wk, nw4);
    split_kernel<3><<<nw4 / 256, 256>>>(Wv, nw4);
    split_kernel<4><<<nw4 / 256, 256>>>(Wo, nw4);

    gemm_qkv<<<dim3(DD/128, MM/128, 3), 128, GSMEM_TOTAL>>>(cosT, sinT);

    flash_mma<<<dim3(SS/128, Bb*HH), 256, FSMEM>>>();

    gemm_out<<<dim3(DD/128, MM/128), 128, GSMEM_TOTAL>>>(out);
}

// round 13
// speedup vs baseline: 1.3716x; 1.3716x over previous
#include <cuda_runtime.h>
#include <cuda_fp16.h>
#include <math.h>
#include <stdint.h>

#define Bb 2
#define SS 2048
#define DD 2048
#define HH 16
#define HDm 128
#define MM (Bb*SS)   // 4096

// ---------------------------------------------------------------------------
// Device-global scratch (no allocations allowed). All fp16 now.
// ---------------------------------------------------------------------------
__device__ __align__(16) __half g_Xh[(size_t)MM*DD], g_Xl[(size_t)MM*DD];
__device__ __align__(16) __half g_Wq[(size_t)DD*DD], g_Wk[(size_t)DD*DD];
__device__ __align__(16) __half g_Wv[(size_t)DD*DD], g_Wo[(size_t)DD*DD];
__device__ __align__(16) __half g_Ch[(size_t)MM*DD], g_Cl[(size_t)MM*DD];

// post-RoPE Q (pre-scaled) / K in fp16 hi/lo, [b,h,s,d]
__device__ __align__(16) __half g_Qh[(size_t)MM*DD], g_Ql[(size_t)MM*DD];
__device__ __align__(16) __half g_Kh[(size_t)MM*DD], g_Kl[(size_t)MM*DD];
// V transposed, [b,h,d,s], single fp16
__device__ __align__(16) __half g_VT[(size_t)MM*DD];

// ---------------------------------------------------------------------------
// helpers (arch-portable PTX only)
// ---------------------------------------------------------------------------
__device__ __forceinline__ uint32_t smem_u32(const void* p) {
    uint32_t a;
    asm("{ .reg .u64 t; cvta.to.shared.u64 t, %1; cvt.u32.u64 %0, t; }"
        : "=r"(a) : "l"(p));
    return a;
}

__device__ __forceinline__ void mma16816(float* c, const uint32_t* a, const uint32_t* b) {
    asm volatile(
        "mma.sync.aligned.m16n8k16.row.col.f32.f16.f16.f32 "
        "{%0,%1,%2,%3}, {%4,%5,%6,%7}, {%8,%9}, {%0,%1,%2,%3};"
        : "+f"(c[0]), "+f"(c[1]), "+f"(c[2]), "+f"(c[3])
        : "r"(a[0]), "r"(a[1]), "r"(a[2]), "r"(a[3]), "r"(b[0]), "r"(b[1]));
}

__device__ __forceinline__ void ldsm4(uint32_t* r, uint32_t addr) {
    asm volatile("ldmatrix.sync.aligned.m8n8.x4.shared.b16 {%0,%1,%2,%3}, [%4];"
        : "=r"(r[0]), "=r"(r[1]), "=r"(r[2]), "=r"(r[3]) : "r"(addr));
}

__device__ __forceinline__ void cpasync16(uint32_t dst, const void* src) {
    asm volatile("cp.async.cg.shared.global [%0], [%1], 16;\n" :: "r"(dst), "l"(src) : "memory");
}

__device__ __forceinline__ uint32_t pack_h2(float a, float b) {
    __half2 t;
    t.x = __float2half(a);
    t.y = __float2half(b);
    return *(uint32_t*)&t;
}

// ---------------------------------------------------------------------------
// fp32 -> fp16 hi/lo splitter for x
// ---------------------------------------------------------------------------
__global__ __launch_bounds__(256) void split_x(const float* __restrict__ src, int n4)
{
    const int i = blockIdx.x * 256 + threadIdx.x;
    if (i >= n4) return;
    const float4 v = ((const float4*)src)[i];
    __half2 h0, h1, l0, l1;
    h0.x = __float2half(v.x); h0.y = __float2half(v.y);
    h1.x = __float2half(v.z); h1.y = __float2half(v.w);
    l0.x = __float2half(v.x - __half2float(h0.x));
    l0.y = __float2half(v.y - __half2float(h0.y));
    l1.x = __float2half(v.z - __half2float(h1.x));
    l1.y = __float2half(v.w - __half2float(h1.y));
    ((__half2*)g_Xh)[i*2]   = h0;
    ((__half2*)g_Xh)[i*2+1] = h1;
    ((__half2*)g_Xl)[i*2]   = l0;
    ((__half2*)g_Xl)[i*2+1] = l1;
}

// fp32 -> single fp16 convert for all 4 weight matrices (blockIdx.y selects)
__global__ __launch_bounds__(256) void convert_w(const float* __restrict__ w0,
                                                 const float* __restrict__ w1,
                                                 const float* __restrict__ w2,
                                                 const float* __restrict__ w3, int n4)
{
    const int i = blockIdx.x * 256 + threadIdx.x;
    if (i >= n4) return;
    const int sel = blockIdx.y;
    const float* src = (sel==0) ? w0 : (sel==1) ? w1 : (sel==2) ? w2 : w3;
    __half* dst = (sel==0) ? g_Wq : (sel==1) ? g_Wk : (sel==2) ? g_Wv : g_Wo;
    const float4 v = ((const float4*)src)[i];
    __half2 h0, h1;
    h0.x = __float2half(v.x); h0.y = __float2half(v.y);
    h1.x = __float2half(v.z); h1.y = __float2half(v.w);
    ((__half2*)dst)[i*2]   = h0;
    ((__half2*)dst)[i*2+1] = h1;
}

// ---------------------------------------------------------------------------
// HMMA GEMM mainloop: C = (Ah + Al) @ B^T, 2-pass, fp16, fp32 accum.
// 128x128 tile, BK=32, 128 threads (4 warps, 64x64 warp tiles), 2-stage
// cp.async, one barrier per chunk, ldmatrix fragments.
// ---------------------------------------------------------------------------
#define TILE_B 10240
#define STAGE_BYTES (3*TILE_B)           // Ah, Al, B
#define GSMEM_TOTAL 67584                // max(2 stages 61440, epi 128*132*4)

__device__ __forceinline__ void stage_load(char* smc, int stage,
    const __half* Ah, const __half* Al, const __half* B,
    size_t arow, size_t brow, int k0, int tid)
{
    const __half* srcs[3] = {Ah, Al, B};
#pragma unroll
    for (int t = 0; t < 3; t++) {
        const size_t rb = (t < 2) ? arow : brow;
        const __half* s = srcs[t];
        char* base = smc + stage*STAGE_BYTES + t*TILE_B;
#pragma unroll
        for (int h = 0; h < 4; h++) {
            const int c = tid + h*128;          // 0..511
            const int row = c >> 2, col = c & 3;
            cpasync16(smem_u32(base + row*80 + col*16), s + (rb + row)*(size_t)DD + k0 + col*8);
        }
    }
}

__device__ __forceinline__ void gemm_mainloop(char* smc,
    const __half* Ah, const __half* Al, const __half* B,
    size_t arow, size_t brow, int tid, float cacc[4][8][4])
{
    const int wid = tid >> 5, lane = tid & 31;
    const int wm = wid >> 1, wn = wid & 1;     // 2x2 warp grid, 64x64 tiles
    const int g = lane >> 2, tg = lane & 3;

    const int rowA = (lane & 7) + ((lane >> 3) & 1) * 8;
    const int khA  = lane >> 4;
    const int rowB = ((lane >> 4) & 1) * 8 + (lane & 7);
    const int khB  = (lane >> 3) & 1;

    const uint32_t sb = smem_u32(smc);
    const uint32_t aoff = (uint32_t)((wm*64 + rowA)*80 + khA*16);
    const uint32_t boff = (uint32_t)((wn*64 + rowB)*80 + khB*16);

    stage_load(smc, 0, Ah, Al, B, arow, brow, 0, tid);
    asm volatile("cp.async.commit_group;\n" ::: "memory");

    for (int ch = 0; ch < 64; ch++) {
        asm volatile("cp.async.wait_group 0;\n" ::: "memory");
        __syncthreads();
        if (ch + 1 < 64) {
            stage_load(smc, (ch+1) & 1, Ah, Al, B, arow, brow, (ch+1)*32, tid);
            asm volatile("cp.async.commit_group;\n" ::: "memory");
        }

        const uint32_t st = sb + (ch & 1)*STAGE_BYTES;
#pragma unroll
        for (int kk2 = 0; kk2 < 2; kk2++) {
            const uint32_t kb = kk2*32;
            uint32_t ah[4][4], al[4][4];
#pragma unroll
            for (int mt = 0; mt < 4; mt++) {
                ldsm4(ah[mt], st + aoff + mt*1280 + kb);
                ldsm4(al[mt], st + TILE_B + aoff + mt*1280 + kb);
            }
#pragma unroll
            for (int p = 0; p < 4; p++) {
                uint32_t bf[4];
                ldsm4(bf, st + 2*TILE_B + boff + p*1280 + kb);
#pragma unroll
                for (int mt = 0; mt < 4; mt++) {
                    mma16816(cacc[mt][2*p],   ah[mt], bf);
                    mma16816(cacc[mt][2*p+1], ah[mt], bf+2);
                    mma16816(cacc[mt][2*p],   al[mt], bf);
                    mma16816(cacc[mt][2*p+1], al[mt], bf+2);
                }
            }
        }
    }

    __syncthreads();
    float* epi = (float*)smc;   // [128][132]
#pragma unroll
    for (int mt = 0; mt < 4; mt++)
#pragma unroll
        for (int nt = 0; nt < 8; nt++) {
            const int r0 = wm*64 + mt*16 + g;
            const int c0 = wn*64 + nt*8 + 2*tg;
            *(float2*)&epi[r0*132 + c0]     = make_float2(cacc[mt][nt][0], cacc[mt][nt][1]);
            *(float2*)&epi[(r0+8)*132 + c0] = make_float2(cacc[mt][nt][2], cacc[mt][nt][3]);
        }
    __syncthreads();
}

// Merged Q/K/V projection GEMM: blockIdx.z selects weight + epilogue.
__global__ __launch_bounds__(128, 3) void gemm_qkv(const float* __restrict__ cosT,
                                                   const float* __restrict__ sinT)
{
    extern __shared__ char smc[];
    const int tid = threadIdx.x;
    const int bn = blockIdx.x, bm = blockIdx.y, sel = blockIdx.z;

    const __half* B = (sel == 0) ? g_Wq : (sel == 1) ? g_Wk : g_Wv;

    float cacc[4][8][4];
#pragma unroll
    for (int mt = 0; mt < 4; mt++)
#pragma unroll
        for (int nt = 0; nt < 8; nt++)
#pragma unroll
            for (int q = 0; q < 4; q++) cacc[mt][nt][q] = 0.f;

    gemm_mainloop(smc, g_Xh, g_Xl, B, (size_t)bm*128, (size_t)bn*128, tid, cacc);

    float* epi = (float*)smc;
    if (sel <= 1) {
        __half* Oh = (sel == 0) ? g_Qh : g_Kh;
        __half* Ol = (sel == 0) ? g_Ql : g_Kl;
        const float qscale = (sel == 0) ? 0.08838834764831845f : 1.0f;  // 1/sqrt(128) folded into Q
        for (int i = tid; i < 128*128; i += 128) {
            const int r = i >> 7, c = i & 127;
            const float v = epi[r*132 + c];
            const int m = bm*128 + r;
            const int b = m >> 11, s = m & 2047;
            const float cs = cosT[s*HDm + c];
            const float sn = sinT[s*HDm + c];
            const float o  = epi[r*132 + (c ^ 64)];
            const float res = ((c < 64) ? (v*cs - o*sn) : (v*cs + o*sn)) * qscale;
            const size_t idx = ((size_t)(b*HH + bn)*SS + s)*HDm + c;
            const __half hh = __float2half(res);
            Oh[idx] = hh;
            Ol[idx] = __float2half(res - __half2float(hh));
        }
    } else {
        const int b = (bm*128) >> 11;
        const int s0 = (bm*128) & 2047;
        for (int i = tid; i < 128*16; i += 128) {
            const int c  = i & 127;
            const int r0 = (i >> 7)*8;
            __half hbuf[8];
#pragma unroll
            for (int j = 0; j < 8; j++)
                hbuf[j] = __float2half(epi[(r0+j)*132 + c]);
            const size_t dst = ((size_t)(b*HH + bn)*HDm + c)*SS + s0 + r0;
            *(uint4*)&g_VT[dst] = *(uint4*)hbuf;
        }
    }
}

// Output GEMM: ctx @ Wo^T -> fp32 out
__global__ __launch_bounds__(128, 3) void gemm_out(float* __restrict__ outp)
{
    extern __shared__ char smc[];
    const int tid = threadIdx.x;
    const int bn = blockIdx.x, bm = blockIdx.y;

    float cacc[4][8][4];
#pragma unroll
    for (int mt = 0; mt < 4; mt++)
#pragma unroll
        for (int nt = 0; nt < 8; nt++)
#pragma unroll
            for (int q = 0; q < 4; q++) cacc[mt][nt][q] = 0.f;

    gemm_mainloop(smc, g_Ch, g_Cl, g_Wo, (size_t)bm*128, (size_t)bn*128, tid, cacc);

    float* epi = (float*)smc;
    for (int i = tid; i < 128*128; i += 128) {
        const int r = i >> 7, c = i & 127;
        outp[(size_t)(bm*128 + r)*DD + bn*128 + c] = epi[r*132 + c];
    }
}

// ---------------------------------------------------------------------------
// Flash attention, fp16 mma.sync. Scores 3-pass (Q,K hi/lo); PV 2-pass
// (P hi/lo x single V). 256 threads, 128 q rows/CTA, 64-row K/V tiles
// double-buffered, one barrier per tile, heavy-first scheduling.
// ---------------------------------------------------------------------------
#define QROWB 272
#define VROWB 144
#define OFF_QH 0
#define OFF_QL (128*QROWB)                 // 34816
#define STG0   (2*128*QROWB)               // 69632
#define SOFF_KH 0
#define SOFF_KL (64*QROWB)                 // 17408
#define SOFF_V  (2*64*QROWB)               // 34816
#define STG_SZ  (2*64*QROWB + 128*VROWB)   // 53248
#define FSMEM   (STG0 + 2*STG_SZ)          // 176128

__device__ __forceinline__ void load_kv(uint32_t sb, int stage,
                                        size_t qkb, size_t vb, int j0, int tid)
{
    const uint32_t base = sb + STG0 + stage*STG_SZ;
#pragma unroll
    for (int j = 0; j < 4; j++) {
        const int idx = j*256 + tid;
        const int row = idx >> 4, c16 = idx & 15;
        cpasync16(base + SOFF_KH + row*QROWB + c16*16, g_Kh + qkb + (size_t)(j0+row)*HDm + c16*8);
        cpasync16(base + SOFF_KL + row*QROWB + c16*16, g_Kl + qkb + (size_t)(j0+row)*HDm + c16*8);
        const int vrow = idx >> 3, c8 = idx & 7;
        cpasync16(base + SOFF_V + vrow*VROWB + c8*16, g_VT + vb + (size_t)vrow*SS + j0 + c8*8);
    }
}

__global__ __launch_bounds__(256) void flash_mma()
{
    extern __shared__ char fs[];
    const uint32_t sb = smem_u32(fs);
    const int tid = threadIdx.x, wid = tid >> 5, lane = tid & 31;
    const int gg = lane >> 2, tg = lane & 3;
    const int bh = blockIdx.y;
    const int q0 = (gridDim.x - 1 - blockIdx.x) * 128;   // heavy-first (LPT)
    const int wq = wid * 16;

    const int rowA = (lane & 7) + ((lane >> 3) & 1) * 8;
    const int khA  = lane >> 4;
    const int rowB = ((lane >> 4) & 1) * 8 + (lane & 7);
    const int khB  = (lane >> 3) & 1;
    const uint32_t qfoff = (uint32_t)((wq + rowA)*QROWB + khA*16);
    const uint32_t kfoff = (uint32_t)(rowB*QROWB + khB*16);
    const uint32_t vfoff = (uint32_t)(rowB*VROWB + khB*16);

    const size_t qkb = (size_t)bh * SS * HDm;   // [bh][s][d]
    const size_t vb  = (size_t)bh * HDm * SS;   // [bh][d][s]

    // load Q hi/lo (128 rows, once)
#pragma unroll
    for (int j = 0; j < 8; j++) {
        const int idx = j*256 + tid;
        const int row = idx >> 4, c16 = idx & 15;
        cpasync16(sb + OFF_QH + row*QROWB + c16*16, g_Qh + qkb + (size_t)(q0+row)*HDm + c16*8);
        cpasync16(sb + OFF_QL + row*QROWB + c16*16, g_Ql + qkb + (size_t)(q0+row)*HDm + c16*8);
    }
    asm volatile("cp.async.commit_group;\n" ::: "memory");

    const int ntiles = q0/64 + 2;
    load_kv(sb, 0, qkb, vb, 0, tid);
    asm volatile("cp.async.commit_group;\n" ::: "memory");

    float m2[2] = {-1e30f, -1e30f}, l2[2] = {0.f, 0.f};
    float oacc[16][4];
#pragma unroll
    for (int i = 0; i < 16; i++)
#pragma unroll
        for (int q = 0; q < 4; q++) oacc[i][q] = 0.f;

    for (int t = 0; t < ntiles; t++) {
        const int j0 = t * 64;
        asm volatile("cp.async.wait_group 0;\n" ::: "memory");
        __syncthreads();
        if (t + 1 < ntiles) {
            load_kv(sb, (t+1) & 1, qkb, vb, (t+1)*64, tid);
            asm volatile("cp.async.commit_group;\n" ::: "memory");
        }

        if (j0 <= q0 + wq + 15) {   // warp not fully masked
            const uint32_t stg = sb + STG0 + (t & 1)*STG_SZ;
            const uint32_t kH = stg + SOFF_KH + kfoff;
            const uint32_t kL = stg + SOFF_KL + kfoff;
            const uint32_t vV = stg + SOFF_V + vfoff;
            const uint32_t qH = sb + OFF_QH + qfoff;
            const uint32_t qL = sb + OFF_QL + qfoff;

            // ---- scores: S = Qh Kh + Qh Kl + Ql Kh (Q pre-scaled) ----
            float sacc[8][4];
#pragma unroll
            for (int nt = 0; nt < 8; nt++)
#pragma unroll
                for (int q = 0; q < 4; q++) sacc[nt][q] = 0.f;

#pragma unroll
            for (int kk2 = 0; kk2 < 8; kk2++) {
                const uint32_t kb = kk2*32;
                uint32_t qh[4], ql[4];
                ldsm4(qh, qH + kb);
                ldsm4(ql, qL + kb);
#pragma unroll
                for (int p = 0; p < 4; p++) {
                    uint32_t kh4[4], kl4[4];
                    ldsm4(kh4, kH + p*(16*QROWB) + kb);
                    ldsm4(kl4, kL + p*(16*QROWB) + kb);
                    mma16816(sacc[2*p],   qh, kh4);
                    mma16816(sacc[2*p+1], qh, kh4+2);
                    mma16816(sacc[2*p],   qh, kl4);
                    mma16816(sacc[2*p+1], qh, kl4+2);
                    mma16816(sacc[2*p],   ql, kh4);
                    mma16816(sacc[2*p+1], ql, kh4+2);
                }
            }

            // ---- mask + online softmax ----
            float corr[2];
#pragma unroll
            for (int h2 = 0; h2 < 2; h2++) {
                const int r = q0 + wq + gg + h2*8;
                float mx = -1e30f;
#pragma unroll
                for (int nt = 0; nt < 8; nt++)
#pragma unroll
                    for (int e = 0; e < 2; e++) {
                        const int col = j0 + nt*8 + 2*tg + e;
                        float v = (col <= r) ? sacc[nt][h2*2+e] : -1e30f;
                        sacc[nt][h2*2+e] = v;
                        mx = fmaxf(mx, v);
                    }
                mx = fmaxf(mx, __shfl_xor_sync(0xffffffffu, mx, 1));
                mx = fmaxf(mx, __shfl_xor_sync(0xffffffffu, mx, 2));
                const float mn = fmaxf(m2[h2], mx);
                corr[h2] = __expf(m2[h2] - mn);
                m2[h2] = mn;
                float rs = 0.f;
#pragma unroll
                for (int nt = 0; nt < 8; nt++)
#pragma unroll
                    for (int e = 0; e < 2; e++) {
                        const float p = __expf(sacc[nt][h2*2+e] - mn);
                        sacc[nt][h2*2+e] = p;
                        rs += p;
                    }
                rs += __shfl_xor_sync(0xffffffffu, rs, 1);
                rs += __shfl_xor_sync(0xffffffffu, rs, 2);
                l2[h2] = l2[h2]*corr[h2] + rs;
            }
#pragma unroll
            for (int nt2 = 0; nt2 < 16; nt2++) {
                oacc[nt2][0] *= corr[0]; oacc[nt2][1] *= corr[0];
                oacc[nt2][2] *= corr[1]; oacc[nt2][3] *= corr[1];
            }

            // ---- pack P hi/lo (fp16) into A fragments ----
            uint32_t aPh[4][4], aPl[4][4];
#pragma unroll
            for (int jp = 0; jp < 4; jp++) {
#pragma unroll
                for (int f = 0; f < 4; f++) {
                    const int nt = 2*jp + (f >> 1);
                    const int e0 = (f & 1)*2;
                    const float p0 = sacc[nt][e0], p1 = sacc[nt][e0+1];
                    const __half h0 = __float2half(p0);
                    const __half h1 = __float2half(p1);
                    __half2 hp; hp.x = h0; hp.y = h1;
                    aPh[jp][f] = *(uint32_t*)&hp;
                    aPl[jp][f] = pack_h2(p0 - __half2float(h0), p1 - __half2float(h1));
                }
            }

            // ---- PV: oacc += Ph V + Pl V (V single fp16) ----
#pragma unroll
            for (int jp = 0; jp < 4; jp++) {
#pragma unroll
                for (int p = 0; p < 8; p++) {
                    uint32_t v4[4];
                    ldsm4(v4, vV + p*(16*VROWB) + jp*32);
                    mma16816(oacc[2*p],   aPh[jp], v4);
                    mma16816(oacc[2*p+1], aPh[jp], v4+2);
                    mma16816(oacc[2*p],   aPl[jp], v4);
                    mma16816(oacc[2*p+1], aPl[jp], v4+2);
                }
            }
        }
    }

    // ---- epilogue: ctx fp16 hi/lo, [b, s, h*HD + d] ----
    const int b = bh / HH, h = bh % HH;
#pragma unroll
    for (int h2 = 0; h2 < 2; h2++) {
        const float inv = 1.f / l2[h2];
        const int r = q0 + wq + gg + h2*8;
        const size_t base = ((size_t)(b*SS + r))*DD + h*HDm;
#pragma unroll
        for (int nt2 = 0; nt2 < 16; nt2++) {
            const int d = nt2*8 + 2*tg;
            const float v0 = oacc[nt2][h2*2]   * inv;
            const float v1 = oacc[nt2][h2*2+1] * inv;
            const __half h0 = __float2half(v0);
            const __half h1 = __float2half(v1);
            __half2 hp; hp.x = h0; hp.y = h1;
            *(uint32_t*)&g_Ch[base + d] = *(uint32_t*)&hp;
            *(uint32_t*)&g_Cl[base + d] =
                pack_h2(v0 - __half2float(h0), v1 - __half2float(h1));
        }
    }
}

// ---------------------------------------------------------------------------
extern "C" void kernel_launch(void* const* d_in, const int* in_sizes, int n_in,
                              void* d_out, int out_size)
{
    const float* x    = (const float*)d_in[0];
    const float* Wq   = (const float*)d_in[1];
    const float* Wk   = (const float*)d_in[2];
    const float* Wv   = (const float*)d_in[3];
    const float* Wo   = (const float*)d_in[4];
    const float* cosT = (const float*)d_in[5];
    const float* sinT = (const float*)d_in[6];
    float* out = (float*)d_out;

    cudaFuncSetAttribute(gemm_qkv, cudaFuncAttributeMaxDynamicSharedMemorySize, GSMEM_TOTAL);
    cudaFuncSetAttribute(gemm_out, cudaFuncAttributeMaxDynamicSharedMemorySize, GSMEM_TOTAL);
    cudaFuncSetAttribute(flash_mma, cudaFuncAttributeMaxDynamicSharedMemorySize, FSMEM);

    const int nx4 = MM * DD / 4;
    const int nw4 = DD * DD / 4;
    split_x<<<nx4 / 256, 256>>>(x, nx4);
    convert_w<<<dim3(nw4 / 256, 4), 256>>>(Wq, Wk, Wv, Wo, nw4);

    gemm_qkv<<<dim3(DD/128, MM/128, 3), 128, GSMEM_TOTAL>>>(cosT, sinT);

    flash_mma<<<dim3(SS/128, Bb*HH), 256, FSMEM>>>();

    gemm_out<<<dim3(DD/128, MM/128), 128, GSMEM_TOTAL>>>(out);
}

// round 15
// speedup vs baseline: 1.5820x; 1.1534x over previous
#include <cuda_runtime.h>
#include <cuda_fp16.h>
#include <math.h>
#include <stdint.h>

#define Bb 2
#define SS 2048
#define DD 2048
#define HH 16
#define HDm 128
#define MM (Bb*SS)   // 4096

// ---------------------------------------------------------------------------
// Device-global scratch (no allocations allowed). All fp16.
// ---------------------------------------------------------------------------
__device__ __align__(16) __half g_Xh[(size_t)MM*DD], g_Xl[(size_t)MM*DD];
__device__ __align__(16) __half g_Wq[(size_t)DD*DD], g_Wk[(size_t)DD*DD];
__device__ __align__(16) __half g_Wv[(size_t)DD*DD], g_Wo[(size_t)DD*DD];
__device__ __align__(16) __half g_C [(size_t)MM*DD];              // ctx, single fp16

// post-RoPE Q (pre-scaled by 1/sqrt(d)*log2e) / K in fp16 hi/lo, [b,h,s,d]
__device__ __align__(16) __half g_Qh[(size_t)MM*DD], g_Ql[(size_t)MM*DD];
__device__ __align__(16) __half g_Kh[(size_t)MM*DD], g_Kl[(size_t)MM*DD];
// V transposed, [b,h,d,s], single fp16
__device__ __align__(16) __half g_VT[(size_t)MM*DD];

// ---------------------------------------------------------------------------
// helpers (arch-portable PTX only)
// ---------------------------------------------------------------------------
__device__ __forceinline__ uint32_t smem_u32(const void* p) {
    uint32_t a;
    asm("{ .reg .u64 t; cvta.to.shared.u64 t, %1; cvt.u32.u64 %0, t; }"
        : "=r"(a) : "l"(p));
    return a;
}

__device__ __forceinline__ void mma16816(float* c, const uint32_t* a, const uint32_t* b) {
    asm volatile(
        "mma.sync.aligned.m16n8k16.row.col.f32.f16.f16.f32 "
        "{%0,%1,%2,%3}, {%4,%5,%6,%7}, {%8,%9}, {%0,%1,%2,%3};"
        : "+f"(c[0]), "+f"(c[1]), "+f"(c[2]), "+f"(c[3])
        : "r"(a[0]), "r"(a[1]), "r"(a[2]), "r"(a[3]), "r"(b[0]), "r"(b[1]));
}

__device__ __forceinline__ void ldsm4(uint32_t* r, uint32_t addr) {
    asm volatile("ldmatrix.sync.aligned.m8n8.x4.shared.b16 {%0,%1,%2,%3}, [%4];"
        : "=r"(r[0]), "=r"(r[1]), "=r"(r[2]), "=r"(r[3]) : "r"(addr));
}

__device__ __forceinline__ void cpasync16(uint32_t dst, const void* src) {
    asm volatile("cp.async.cg.shared.global [%0], [%1], 16;\n" :: "r"(dst), "l"(src) : "memory");
}

__device__ __forceinline__ float fex2(float x) {
    float r;
    asm("ex2.approx.ftz.f32 %0, %1;" : "=f"(r) : "f"(x));
    return r;
}

// ---------------------------------------------------------------------------
// fp32 -> fp16 hi/lo splitter for x
// ---------------------------------------------------------------------------
__global__ __launch_bounds__(256) void split_x(const float* __restrict__ src, int n4)
{
    const int i = blockIdx.x * 256 + threadIdx.x;
    if (i >= n4) return;
    const float4 v = ((const float4*)src)[i];
    __half2 h0, h1, l0, l1;
    h0.x = __float2half(v.x); h0.y = __float2half(v.y);
    h1.x = __float2half(v.z); h1.y = __float2half(v.w);
    l0.x = __float2half(v.x - __half2float(h0.x));
    l0.y = __float2half(v.y - __half2float(h0.y));
    l1.x = __float2half(v.z - __half2float(h1.x));
    l1.y = __float2half(v.w - __half2float(h1.y));
    ((__half2*)g_Xh)[i*2]   = h0;
    ((__half2*)g_Xh)[i*2+1] = h1;
    ((__half2*)g_Xl)[i*2]   = l0;
    ((__half2*)g_Xl)[i*2+1] = l1;
}

// fp32 -> single fp16 convert for all 4 weight matrices (blockIdx.y selects)
__global__ __launch_bounds__(256) void convert_w(const float* __restrict__ w0,
                                                 const float* __restrict__ w1,
                                                 const float* __restrict__ w2,
                                                 const float* __restrict__ w3, int n4)
{
    const int i = blockIdx.x * 256 + threadIdx.x;
    if (i >= n4) return;
    const int sel = blockIdx.y;
    const float* src = (sel==0) ? w0 : (sel==1) ? w1 : (sel==2) ? w2 : w3;
    __half* dst = (sel==0) ? g_Wq : (sel==1) ? g_Wk : (sel==2) ? g_Wv : g_Wo;
    const float4 v = ((const float4*)src)[i];
    __half2 h0, h1;
    h0.x = __float2half(v.x); h0.y = __float2half(v.y);
    h1.x = __float2half(v.z); h1.y = __float2half(v.w);
    ((__half2*)dst)[i*2]   = h0;
    ((__half2*)dst)[i*2+1] = h1;
}

// ---------------------------------------------------------------------------
// HMMA GEMM mainloop. 128x128 tile, BK=32, 128 threads (4 warps, 64x64
// warp tiles), 2-stage cp.async, one barrier per chunk, ldmatrix fragments.
// SPLIT_A=1: C = (Ah+Al) @ B^T (2-pass);  SPLIT_A=0: C = A @ B^T (1-pass).
// ---------------------------------------------------------------------------
#define TILE_B 10240
#define GSMEM_TOTAL 67584                // epi 128*132*4 dominates

template<int SPLIT_A>
__device__ __forceinline__ void stage_load(char* smc, int stage,
    const __half* Ah, const __half* Al, const __half* B,
    size_t arow, size_t brow, int k0, int tid)
{
    const int NT = SPLIT_A ? 3 : 2;
    const int STB = NT * TILE_B;
    const __half* srcs[3] = {Ah, SPLIT_A ? Al : B, B};
#pragma unroll
    for (int t = 0; t < NT; t++) {
        const size_t rb = (t < NT-1) ? arow : brow;
        const __half* s = srcs[t];
        char* base = smc + stage*STB + t*TILE_B;
#pragma unroll
        for (int h = 0; h < 4; h++) {
            const int c = tid + h*128;          // 0..511
            const int row = c >> 2, col = c & 3;
            cpasync16(smem_u32(base + row*80 + col*16), s + (rb + row)*(size_t)DD + k0 + col*8);
        }
    }
}

template<int SPLIT_A>
__device__ __forceinline__ void gemm_mainloop(char* smc,
    const __half* Ah, const __half* Al, const __half* B,
    size_t arow, size_t brow, int tid, float cacc[4][8][4])
{
    const int wid = tid >> 5, lane = tid & 31;
    const int wm = wid >> 1, wn = wid & 1;     // 2x2 warp grid, 64x64 tiles
    const int g = lane >> 2, tg = lane & 3;
    const int STB = (SPLIT_A ? 3 : 2) * TILE_B;
    const int BOFFT = (SPLIT_A ? 2 : 1) * TILE_B;

    const int rowA = (lane & 7) + ((lane >> 3) & 1) * 8;
    const int khA  = lane >> 4;
    const int rowB = ((lane >> 4) & 1) * 8 + (lane & 7);
    const int khB  = (lane >> 3) & 1;

    const uint32_t sb = smem_u32(smc);
    const uint32_t aoff = (uint32_t)((wm*64 + rowA)*80 + khA*16);
    const uint32_t boff = (uint32_t)((wn*64 + rowB)*80 + khB*16);

    stage_load<SPLIT_A>(smc, 0, Ah, Al, B, arow, brow, 0, tid);
    asm volatile("cp.async.commit_group;\n" ::: "memory");

    for (int ch = 0; ch < 64; ch++) {
        asm volatile("cp.async.wait_group 0;\n" ::: "memory");
        __syncthreads();
        if (ch + 1 < 64) {
            stage_load<SPLIT_A>(smc, (ch+1) & 1, Ah, Al, B, arow, brow, (ch+1)*32, tid);
            asm volatile("cp.async.commit_group;\n" ::: "memory");
        }

        const uint32_t st = sb + (ch & 1)*STB;
#pragma unroll
        for (int kk2 = 0; kk2 < 2; kk2++) {
            const uint32_t kb = kk2*32;
            uint32_t ah[4][4], al[4][4];
#pragma unroll
            for (int mt = 0; mt < 4; mt++) {
                ldsm4(ah[mt], st + aoff + mt*1280 + kb);
                if (SPLIT_A) ldsm4(al[mt], st + TILE_B + aoff + mt*1280 + kb);
            }
#pragma unroll
            for (int p = 0; p < 4; p++) {
                uint32_t bf[4];
                ldsm4(bf, st + BOFFT + boff + p*1280 + kb);
#pragma unroll
                for (int mt = 0; mt < 4; mt++) {
                    mma16816(cacc[mt][2*p],   ah[mt], bf);
                    mma16816(cacc[mt][2*p+1], ah[mt], bf+2);
                    if (SPLIT_A) {
                        mma16816(cacc[mt][2*p],   al[mt], bf);
                        mma16816(cacc[mt][2*p+1], al[mt], bf+2);
                    }
                }
            }
        }
    }

    __syncthreads();
    float* epi = (float*)smc;   // [128][132]
#pragma unroll
    for (int mt = 0; mt < 4; mt++)
#pragma unroll
        for (int nt = 0; nt < 8; nt++) {
            const int r0 = wm*64 + mt*16 + g;
            const int c0 = wn*64 + nt*8 + 2*tg;
            *(float2*)&epi[r0*132 + c0]     = make_float2(cacc[mt][nt][0], cacc[mt][nt][1]);
            *(float2*)&epi[(r0+8)*132 + c0] = make_float2(cacc[mt][nt][2], cacc[mt][nt][3]);
        }
    __syncthreads();
}

// Merged Q/K/V projection GEMM: blockIdx.z selects weight + epilogue.
__global__ __launch_bounds__(128, 3) void gemm_qkv(const float* __restrict__ cosT,
                                                   const float* __restrict__ sinT)
{
    extern __shared__ char smc[];
    const int tid = threadIdx.x;
    const int bn = blockIdx.x, bm = blockIdx.y, sel = blockIdx.z;

    const __half* B = (sel == 0) ? g_Wq : (sel == 1) ? g_Wk : g_Wv;

    float cacc[4][8][4];
#pragma unroll
    for (int mt = 0; mt < 4; mt++)
#pragma unroll
        for (int nt = 0; nt < 8; nt++)
#pragma unroll
            for (int q = 0; q < 4; q++) cacc[mt][nt][q] = 0.f;

    gemm_mainloop<1>(smc, g_Xh, g_Xl, B, (size_t)bm*128, (size_t)bn*128, tid, cacc);

    float* epi = (float*)smc;
    if (sel <= 1) {
        __half* Oh = (sel == 0) ? g_Qh : g_Kh;
        __half* Ol = (sel == 0) ? g_Ql : g_Kl;
        // Q pre-scale: 1/sqrt(128) * log2(e)  (scores computed in log2 domain)
        const float qscale = (sel == 0) ? 0.12751740948158872f : 1.0f;
        for (int i = tid; i < 128*128; i += 128) {
            const int r = i >> 7, c = i & 127;
            const float v = epi[r*132 + c];
            const int m = bm*128 + r;
            const int b = m >> 11, s = m & 2047;
            const float cs = cosT[s*HDm + c];
            const float sn = sinT[s*HDm + c];
            const float o  = epi[r*132 + (c ^ 64)];
            const float res = ((c < 64) ? (v*cs - o*sn) : (v*cs + o*sn)) * qscale;
            const size_t idx = ((size_t)(b*HH + bn)*SS + s)*HDm + c;
            const __half hh = __float2half(res);
            Oh[idx] = hh;
            Ol[idx] = __float2half(res - __half2float(hh));
        }
    } else {
        const int b = (bm*128) >> 11;
        const int s0 = (bm*128) & 2047;
        for (int i = tid; i < 128*16; i += 128) {
            const int c  = i & 127;
            const int r0 = (i >> 7)*8;
            __half hbuf[8];
#pragma unroll
            for (int j = 0; j < 8; j++)
                hbuf[j] = __float2half(epi[(r0+j)*132 + c]);
            const size_t dst = ((size_t)(b*HH + bn)*HDm + c)*SS + s0 + r0;
            *(uint4*)&g_VT[dst] = *(uint4*)hbuf;
        }
    }
}

// Output GEMM: ctx (single fp16) @ Wo^T -> fp32 out.  1-pass.
__global__ __launch_bounds__(128, 3) void gemm_out(float* __restrict__ outp)
{
    extern __shared__ char smc[];
    const int tid = threadIdx.x;
    const int bn = blockIdx.x, bm = blockIdx.y;

    float cacc[4][8][4];
#pragma unroll
    for (int mt = 0; mt < 4; mt++)
#pragma unroll
        for (int nt = 0; nt < 8; nt++)
#pragma unroll
            for (int q = 0; q < 4; q++) cacc[mt][nt][q] = 0.f;

    gemm_mainloop<0>(smc, g_C, nullptr, g_Wo, (size_t)bm*128, (size_t)bn*128, tid, cacc);

    float* epi = (float*)smc;
    for (int i = tid; i < 128*128; i += 128) {
        const int r = i >> 7, c = i & 127;
        outp[(size_t)(bm*128 + r)*DD + bn*128 + c] = epi[r*132 + c];
    }
}

// ---------------------------------------------------------------------------
// Flash attention, fp16 mma.sync. Scores 3-pass (Q,K hi/lo, log2 domain);
// PV 1-pass (P single fp16 x single V). 256 threads, 128 q rows/CTA,
// 64-row K/V tiles double-buffered, one barrier per tile, heavy-first.
// ---------------------------------------------------------------------------
#define QROWB 272
#define VROWB 144
#define OFF_QH 0
#define OFF_QL (128*QROWB)                 // 34816
#define STG0   (2*128*QROWB)               // 69632
#define SOFF_KH 0
#define SOFF_KL (64*QROWB)                 // 17408
#define SOFF_V  (2*64*QROWB)               // 34816
#define STG_SZ  (2*64*QROWB + 128*VROWB)   // 53248
#define FSMEM   (STG0 + 2*STG_SZ)          // 176128

__device__ __forceinline__ void load_kv(uint32_t sb, int stage,
                                        size_t qkb, size_t vb, int j0, int tid)
{
    const uint32_t base = sb + STG0 + stage*STG_SZ;
#pragma unroll
    for (int j = 0; j < 4; j++) {
        const int idx = j*256 + tid;
        const int row = idx >> 4, c16 = idx & 15;
        cpasync16(base + SOFF_KH + row*QROWB + c16*16, g_Kh + qkb + (size_t)(j0+row)*HDm + c16*8);
        cpasync16(base + SOFF_KL + row*QROWB + c16*16, g_Kl + qkb + (size_t)(j0+row)*HDm + c16*8);
        const int vrow = idx >> 3, c8 = idx & 7;
        cpasync16(base + SOFF_V + vrow*VROWB + c8*16, g_VT + vb + (size_t)vrow*SS + j0 + c8*8);
    }
}

__global__ __launch_bounds__(256) void flash_mma()
{
    extern __shared__ char fs[];
    const uint32_t sb = smem_u32(fs);
    const int tid = threadIdx.x, wid = tid >> 5, lane = tid & 31;
    const int gg = lane >> 2, tg = lane & 3;
    const int bh = blockIdx.y;
    const int q0 = (gridDim.x - 1 - blockIdx.x) * 128;   // heavy-first (LPT)
    const int wq = wid * 16;

    const int rowA = (lane & 7) + ((lane >> 3) & 1) * 8;
    const int khA  = lane >> 4;
    const int rowB = ((lane >> 4) & 1) * 8 + (lane & 7);
    const int khB  = (lane >> 3) & 1;
    const uint32_t qfoff = (uint32_t)((wq + rowA)*QROWB + khA*16);
    const uint32_t kfoff = (uint32_t)(rowB*QROWB + khB*16);
    const uint32_t vfoff = (uint32_t)(rowB*VROWB + khB*16);

    const size_t qkb = (size_t)bh * SS * HDm;   // [bh][s][d]
    const size_t vb  = (size_t)bh * HDm * SS;   // [bh][d][s]

    // load Q hi/lo (128 rows, once)
#pragma unroll
    for (int j = 0; j < 8; j++) {
        const int idx = j*256 + tid;
        const int row = idx >> 4, c16 = idx & 15;
        cpasync16(sb + OFF_QH + row*QROWB + c16*16, g_Qh + qkb + (size_t)(q0+row)*HDm + c16*8);
        cpasync16(sb + OFF_QL + row*QROWB + c16*16, g_Ql + qkb + (size_t)(q0+row)*HDm + c16*8);
    }
    asm volatile("cp.async.commit_group;\n" ::: "memory");

    const int ntiles = q0/64 + 2;
    load_kv(sb, 0, qkb, vb, 0, tid);
    asm volatile("cp.async.commit_group;\n" ::: "memory");

    float m2[2] = {-1e30f, -1e30f}, l2[2] = {0.f, 0.f};
    float oacc[16][4];
#pragma unroll
    for (int i = 0; i < 16; i++)
#pragma unroll
        for (int q = 0; q < 4; q++) oacc[i][q] = 0.f;

    for (int t = 0; t < ntiles; t++) {
        const int j0 = t * 64;
        asm volatile("cp.async.wait_group 0;\n" ::: "memory");
        __syncthreads();
        if (t + 1 < ntiles) {
            load_kv(sb, (t+1) & 1, qkb, vb, (t+1)*64, tid);
            asm volatile("cp.async.commit_group;\n" ::: "memory");
        }

        if (j0 <= q0 + wq + 15) {   // warp not fully masked
            const bool interior = (j0 + 63 <= q0 + wq);  // no masking needed
            const uint32_t stg = sb + STG0 + (t & 1)*STG_SZ;
            const uint32_t kH = stg + SOFF_KH + kfoff;
            const uint32_t kL = stg + SOFF_KL + kfoff;
            const uint32_t vV = stg + SOFF_V + vfoff;
            const uint32_t qH = sb + OFF_QH + qfoff;
            const uint32_t qL = sb + OFF_QL + qfoff;

            // ---- scores (log2 domain): S = Qh Kh + Qh Kl + Ql Kh ----
            float sacc[8][4];
#pragma unroll
            for (int nt = 0; nt < 8; nt++)
#pragma unroll
                for (int q = 0; q < 4; q++) sacc[nt][q] = 0.f;

#pragma unroll
            for (int kk2 = 0; kk2 < 8; kk2++) {
                const uint32_t kb = kk2*32;
                uint32_t qh[4], ql[4];
                ldsm4(qh, qH + kb);
                ldsm4(ql, qL + kb);
#pragma unroll
                for (int p = 0; p < 4; p++) {
                    uint32_t kh4[4], kl4[4];
                    ldsm4(kh4, kH + p*(16*QROWB) + kb);
                    ldsm4(kl4, kL + p*(16*QROWB) + kb);
                    mma16816(sacc[2*p],   qh, kh4);
                    mma16816(sacc[2*p+1], qh, kh4+2);
                    mma16816(sacc[2*p],   qh, kl4);
                    mma16816(sacc[2*p+1], qh, kl4+2);
                    mma16816(sacc[2*p],   ql, kh4);
                    mma16816(sacc[2*p+1], ql, kh4+2);
                }
            }

            // ---- mask + online softmax (exp2; rows gg and gg+8) ----
            float corr[2];
#pragma unroll
            for (int h2 = 0; h2 < 2; h2++) {
                const int r = q0 + wq + gg + h2*8;
                float mx = -1e30f;
                if (interior) {
#pragma unroll
                    for (int nt = 0; nt < 8; nt++)
#pragma unroll
                        for (int e = 0; e < 2; e++)
                            mx = fmaxf(mx, sacc[nt][h2*2+e]);
                } else {
#pragma unroll
                    for (int nt = 0; nt < 8; nt++)
#pragma unroll
                        for (int e = 0; e < 2; e++) {
                            const int col = j0 + nt*8 + 2*tg + e;
                            float v = (col <= r) ? sacc[nt][h2*2+e] : -1e30f;
                            sacc[nt][h2*2+e] = v;
                            mx = fmaxf(mx, v);
                        }
                }
                mx = fmaxf(mx, __shfl_xor_sync(0xffffffffu, mx, 1));
                mx = fmaxf(mx, __shfl_xor_sync(0xffffffffu, mx, 2));
                const float mn = fmaxf(m2[h2], mx);
                corr[h2] = fex2(m2[h2] - mn);
                m2[h2] = mn;
                float rs = 0.f;
#pragma unroll
                for (int nt = 0; nt < 8; nt++)
#pragma unroll
                    for (int e = 0; e < 2; e++) {
                        const float p = fex2(sacc[nt][h2*2+e] - mn);
                        sacc[nt][h2*2+e] = p;
                        rs += p;
                    }
                rs += __shfl_xor_sync(0xffffffffu, rs, 1);
                rs += __shfl_xor_sync(0xffffffffu, rs, 2);
                l2[h2] = l2[h2]*corr[h2] + rs;
            }
#pragma unroll
            for (int nt2 = 0; nt2 < 16; nt2++) {
                oacc[nt2][0] *= corr[0]; oacc[nt2][1] *= corr[0];
                oacc[nt2][2] *= corr[1]; oacc[nt2][3] *= corr[1];
            }

            // ---- pack P (single fp16) into A fragments ----
            uint32_t aP[4][4];
#pragma unroll
            for (int jp = 0; jp < 4; jp++) {
#pragma unroll
                for (int f = 0; f < 4; f++) {
                    const int nt = 2*jp + (f >> 1);
                    const int e0 = (f & 1)*2;
                    __half2 hp;
                    hp.x = __float2half(sacc[nt][e0]);
                    hp.y = __float2half(sacc[nt][e0+1]);
                    aP[jp][f] = *(uint32_t*)&hp;
                }
            }

            // ---- PV: oacc += P V (single pass) ----
#pragma unroll
            for (int jp = 0; jp < 4; jp++) {
#pragma unroll
                for (int p = 0; p < 8; p++) {
                    uint32_t v4[4];
                    ldsm4(v4, vV + p*(16*VROWB) + jp*32);
                    mma16816(oacc[2*p],   aP[jp], v4);
                    mma16816(oacc[2*p+1], aP[jp], v4+2);
                }
            }
        }
    }

    // ---- epilogue: ctx single fp16, [b, s, h*HD + d] ----
    const int b = bh / HH, h = bh % HH;
#pragma unroll
    for (int h2 = 0; h2 < 2; h2++) {
        const float inv = 1.f / l2[h2];
        const int r = q0 + wq + gg + h2*8;
        const size_t base = ((size_t)(b*SS + r))*DD + h*HDm;
#pragma unroll
        for (int nt2 = 0; nt2 < 16; nt2++) {
            const int d = nt2*8 + 2*tg;
            __half2 hp;
            hp.x = __float2half(oacc[nt2][h2*2]   * inv);
            hp.y = __float2half(oacc[nt2][h2*2+1] * inv);
            *(uint32_t*)&g_C[base + d] = *(uint32_t*)&hp;
        }
    }
}

// ---------------------------------------------------------------------------
extern "C" void kernel_launch(void* const* d_in, const int* in_sizes, int n_in,
                              void* d_out, int out_size)
{
    const float* x    = (const float*)d_in[0];
    const float* Wq   = (const float*)d_in[1];
    const float* Wk   = (const float*)d_in[2];
    const float* Wv   = (const float*)d_in[3];
    const float* Wo   = (const float*)d_in[4];
    const float* cosT = (const float*)d_in[5];
    const float* sinT = (const float*)d_in[6];
    float* out = (float*)d_out;

    cudaFuncSetAttribute(gemm_qkv, cudaFuncAttributeMaxDynamicSharedMemorySize, GSMEM_TOTAL);
    cudaFuncSetAttribute(gemm_out, cudaFuncAttributeMaxDynamicSharedMemorySize, GSMEM_TOTAL);
    cudaFuncSetAttribute(flash_mma, cudaFuncAttributeMaxDynamicSharedMemorySize, FSMEM);

    const int nx4 = MM * DD / 4;
    const int nw4 = DD * DD / 4;
    split_x<<<nx4 / 256, 256>>>(x, nx4);
    convert_w<<<dim3(nw4 / 256, 4), 256>>>(Wq, Wk, Wv, Wo, nw4);

    gemm_qkv<<<dim3(DD/128, MM/128, 3), 128, GSMEM_TOTAL>>>(cosT, sinT);

    flash_mma<<<dim3(SS/128, Bb*HH), 256, FSMEM>>>();

    gemm_out<<<dim3(DD/128, MM/128), 128, GSMEM_TOTAL>>>(out);
}